// round 9
// baseline (speedup 1.0000x reference)
#include <cuda_runtime.h>
#include <cuda_fp16.h>
#include <math.h>
#include <stdint.h>

// Problem constants (fixed shapes)
#define BSZ 2
#define HWN 4096
#define CD  512
#define NBROWS (BSZ*HWN)      // 8192
#define NGROUPS 32

// ---------------------------------------------------------------------------
// Scratch (device globals; no allocations)
// ---------------------------------------------------------------------------
__device__ float g_xn  [(size_t)NBROWS*CD];           // xn; later reused as "ao"
__device__ float g_qkv [(size_t)3*NBROWS*CD];         // q | k | v
__device__ float g_attn[(size_t)BSZ*HWN*HWN];         // 134 MB
__device__ float g_vt  [(size_t)BSZ*CD*HWN];          // v transposed per batch
__device__ float g_wt  [(size_t)4*CD*CD];             // wq^T | wk^T | wv^T | wp^T
__device__ float g_mean[BSZ*NGROUPS];
__device__ float g_rstd[BSZ*NGROUPS];

// ---------------------------------------------------------------------------
// fp16 helpers (portable sm_80+ mma.sync path; NO 'a'-suffix features)
// ---------------------------------------------------------------------------
__device__ __forceinline__ uint32_t packh2(float lo, float hi) {
    __half2 h = __float22half2_rn(make_float2(lo, hi));
    return *(uint32_t*)&h;
}
__device__ __forceinline__ uint2 pack4(float4 v) {
    return make_uint2(packh2(v.x, v.y), packh2(v.z, v.w));
}
__device__ __forceinline__ void mma_f16(float c[4], const uint32_t a[4], const uint32_t b[2]) {
    asm volatile(
        "mma.sync.aligned.m16n8k16.row.col.f32.f16.f16.f32 "
        "{%0,%1,%2,%3}, {%4,%5,%6,%7}, {%8,%9}, {%0,%1,%2,%3};"
        : "+f"(c[0]), "+f"(c[1]), "+f"(c[2]), "+f"(c[3])
        : "r"(a[0]), "r"(a[1]), "r"(a[2]), "r"(a[3]), "r"(b[0]), "r"(b[1]));
}

// ---------------------------------------------------------------------------
// GroupNorm
// ---------------------------------------------------------------------------
__global__ void gn_stats(const float* __restrict__ x,
                         float* __restrict__ mean, float* __restrict__ rstd) {
    __shared__ float shs[8], shss[8];
    const int bg = blockIdx.x;
    const int b = bg >> 5, g = bg & 31;
    const float4* xb = (const float4*)x + (size_t)b*524288 + g*4;
    float s = 0.f, ss = 0.f;
    for (int i = threadIdx.x; i < 16384; i += 256) {
        int n = i >> 2, j = i & 3;
        float4 vv = xb[(size_t)n*128 + j];
        s  += vv.x + vv.y + vv.z + vv.w;
        ss += vv.x*vv.x + vv.y*vv.y + vv.z*vv.z + vv.w*vv.w;
    }
    #pragma unroll
    for (int o = 16; o; o >>= 1) {
        s  += __shfl_xor_sync(0xffffffffu, s,  o);
        ss += __shfl_xor_sync(0xffffffffu, ss, o);
    }
    if ((threadIdx.x & 31) == 0) { shs[threadIdx.x>>5] = s; shss[threadIdx.x>>5] = ss; }
    __syncthreads();
    if (threadIdx.x == 0) {
        s = 0.f; ss = 0.f;
        #pragma unroll
        for (int w = 0; w < 8; w++) { s += shs[w]; ss += shss[w]; }
        float m   = s * (1.f/65536.f);
        float var = ss * (1.f/65536.f) - m*m;
        mean[bg] = m;
        rstd[bg] = rsqrtf(var + 1e-5f);
    }
}

__global__ void gn_norm(const float* __restrict__ x,
                        const float* __restrict__ gamma, const float* __restrict__ beta,
                        const float* __restrict__ mean, const float* __restrict__ rstd,
                        float* __restrict__ xn) {
    const int idx = blockIdx.x * blockDim.x + threadIdx.x;
    float4 v = ((const float4*)x)[idx];
    const int c4 = idx & 127;
    const int b  = idx >> 19;
    const int g  = c4 >> 2;
    const int bg = b * 32 + g;
    const float m = mean[bg], r = rstd[bg];
    const float4 ga = ((const float4*)gamma)[c4];
    const float4 be = ((const float4*)beta)[c4];
    float4 o;
    o.x = (v.x - m) * r * ga.x + be.x;
    o.y = (v.y - m) * r * ga.y + be.y;
    o.z = (v.z - m) * r * ga.z + be.z;
    o.w = (v.w - m) * r * ga.w + be.w;
    ((float4*)xn)[idx] = o;
}

// ---------------------------------------------------------------------------
// Tiled transpose: out[c][r] = in[r][c].  block (32,8), grid (cols/32, rows/32, nz)
// ---------------------------------------------------------------------------
__global__ void transpose_kernel(const float* __restrict__ in, float* __restrict__ out,
                                 int rows, int cols, size_t zInStride, size_t zOutStride) {
    __shared__ float t[32][33];
    const float* inz = in + blockIdx.z * zInStride;
    float* outz = out + blockIdx.z * zOutStride;
    int c0 = blockIdx.x * 32, r0 = blockIdx.y * 32;
    int x = threadIdx.x;
    #pragma unroll
    for (int y = threadIdx.y; y < 32; y += 8)
        t[y][x] = inz[(size_t)(r0 + y) * cols + c0 + x];
    __syncthreads();
    #pragma unroll
    for (int y = threadIdx.y; y < 32; y += 8)
        outz[(size_t)(c0 + y) * rows + r0 + x] = t[x][y];
}

// ---------------------------------------------------------------------------
// Tensor-core fp16 NT GEMM (software-pipelined, double-buffered SMEM):
//   Cm[m][n] = alpha * sum_k A[m][k] * Bt[n][k]  (+bias[n]) (+res[m][n])
// CTA tile 128x128, BK=16 (one m16n8k16 k-step), 256 threads = 8 warps (2m x 4n),
// warp tile 64x32.  SMEM: packed half2 along k, 8 words/row + pad -> stride 12
// (conflict-free: 12*gid+tg mod 32 covers all banks).  fp32 accum + epilogue.
// blockIdx.z selects batch via zA/zB/zC element strides.
// ---------------------------------------------------------------------------
#define SMS 12   // smem row stride in 32-bit words (8 data + 4 pad)

template<bool BIAS, bool RES>
__global__ __launch_bounds__(256)
void gemm_mma(const float* __restrict__ A, const float* __restrict__ Bt,
              const float* __restrict__ bias, const float* __restrict__ res,
              float* __restrict__ Cm,
              int K, int lda, int ldb, int ldc, float alpha,
              size_t zA, size_t zB, size_t zC) {
    __shared__ uint32_t As[2][128 * SMS];
    __shared__ uint32_t Bs[2][128 * SMS];

    A  += blockIdx.z * zA;
    Bt += blockIdx.z * zB;
    Cm += blockIdx.z * zC;
    const float* resz = RES ? (res + blockIdx.z * zC) : res;

    const int tid = threadIdx.x;
    const int wid = tid >> 5;
    const int lane = tid & 31;
    const int gid = lane >> 2;        // 0..7
    const int tg  = lane & 3;         // 0..3
    const int wm = (wid & 1) * 64;    // warp m offset
    const int wn = (wid >> 1) * 32;   // warp n offset
    const int rowBlock = blockIdx.y * 128;
    const int colBlock = blockIdx.x * 128;

    // staging coords: each thread owns rows {grow, grow+64}, 4 k-cols at gc4
    const int grow = tid >> 2;        // 0..63
    const int gc4  = (tid & 3) * 4;   // 0,4,8,12 (fp32 k index)
    const int gc2  = (tid & 3) * 2;   // 0,2,4,6  (packed half2 word index)

    const float* Ap0 = A  + (size_t)(rowBlock + grow)      * lda + gc4;
    const float* Ap1 = A  + (size_t)(rowBlock + grow + 64) * lda + gc4;
    const float* Bp0 = Bt + (size_t)(colBlock + grow)      * ldb + gc4;
    const float* Bp1 = Bt + (size_t)(colBlock + grow + 64) * ldb + gc4;

    float acc[4][4][4];
    #pragma unroll
    for (int mi = 0; mi < 4; mi++)
        #pragma unroll
        for (int ni = 0; ni < 4; ni++)
            #pragma unroll
            for (int r = 0; r < 4; r++) acc[mi][ni][r] = 0.f;

    float4 pa0, pa1, pb0, pb1;

    // prologue: load + store tile 0
    pa0 = *(const float4*)(Ap0);
    pa1 = *(const float4*)(Ap1);
    pb0 = *(const float4*)(Bp0);
    pb1 = *(const float4*)(Bp1);
    *(uint2*)&As[0][grow * SMS + gc2]        = pack4(pa0);
    *(uint2*)&As[0][(grow + 64) * SMS + gc2] = pack4(pa1);
    *(uint2*)&Bs[0][grow * SMS + gc2]        = pack4(pb0);
    *(uint2*)&Bs[0][(grow + 64) * SMS + gc2] = pack4(pb1);
    __syncthreads();

    const int T = K >> 4;
    int p = 0;
    for (int t = 0; t < T; t++) {
        // prefetch next tile into registers (overlaps with MMAs below)
        if (t + 1 < T) {
            const int kn = (t + 1) << 4;
            pa0 = *(const float4*)(Ap0 + kn);
            pa1 = *(const float4*)(Ap1 + kn);
            pb0 = *(const float4*)(Bp0 + kn);
            pb1 = *(const float4*)(Bp1 + kn);
        }

        // compute current tile from SMEM buffer p (one k16 step)
        const uint32_t* Ab = As[p];
        const uint32_t* Bb = Bs[p];
        {
            uint32_t af[4][4];
            #pragma unroll
            for (int mi = 0; mi < 4; mi++) {
                const int base = (wm + mi * 16 + gid) * SMS;
                af[mi][0] = Ab[base + tg];
                af[mi][1] = Ab[base + 8 * SMS + tg];
                af[mi][2] = Ab[base + tg + 4];
                af[mi][3] = Ab[base + 8 * SMS + tg + 4];
            }
            uint32_t bf[4][2];
            #pragma unroll
            for (int ni = 0; ni < 4; ni++) {
                const int base = (wn + ni * 8 + gid) * SMS;
                bf[ni][0] = Bb[base + tg];
                bf[ni][1] = Bb[base + tg + 4];
            }
            #pragma unroll
            for (int mi = 0; mi < 4; mi++)
                #pragma unroll
                for (int ni = 0; ni < 4; ni++)
                    mma_f16(acc[mi][ni], af[mi], bf[ni]);
        }

        // stage next tile into the other buffer; single barrier per iteration
        if (t + 1 < T) {
            const int q = p ^ 1;
            *(uint2*)&As[q][grow * SMS + gc2]        = pack4(pa0);
            *(uint2*)&As[q][(grow + 64) * SMS + gc2] = pack4(pa1);
            *(uint2*)&Bs[q][grow * SMS + gc2]        = pack4(pb0);
            *(uint2*)&Bs[q][(grow + 64) * SMS + gc2] = pack4(pb1);
            __syncthreads();
            p = q;
        }
    }

    // epilogue: c0,c1 -> (row, 2tg..2tg+1); c2,c3 -> (row+8, same cols)
    #pragma unroll
    for (int mi = 0; mi < 4; mi++) {
        #pragma unroll
        for (int half = 0; half < 2; half++) {
            const size_t r = (size_t)(rowBlock + wm + mi * 16 + gid + half * 8);
            #pragma unroll
            for (int ni = 0; ni < 4; ni++) {
                const size_t c = (size_t)(colBlock + wn + ni * 8 + 2 * tg);
                float2 o;
                o.x = acc[mi][ni][half * 2 + 0] * alpha;
                o.y = acc[mi][ni][half * 2 + 1] * alpha;
                if (BIAS) {
                    const float2 bb = *(const float2*)(bias + c);
                    o.x += bb.x; o.y += bb.y;
                }
                if (RES) {
                    const float2 rr = *(const float2*)(resz + r * ldc + c);
                    o.x += rr.x; o.y += rr.y;
                }
                *(float2*)(Cm + r * ldc + c) = o;
            }
        }
    }
}

// ---------------------------------------------------------------------------
// Row softmax (in-place)
// ---------------------------------------------------------------------------
__global__ void softmax_kernel(float* __restrict__ S) {
    __shared__ float sh[8];
    const size_t row = blockIdx.x;
    float* p = S + row * 4096;
    const int tid = threadIdx.x;
    float4 v[4];
    float mx = -1e30f;
    #pragma unroll
    for (int i = 0; i < 4; i++) {
        v[i] = ((const float4*)p)[tid + i*256];
        mx = fmaxf(mx, fmaxf(fmaxf(v[i].x, v[i].y), fmaxf(v[i].z, v[i].w)));
    }
    #pragma unroll
    for (int o = 16; o; o >>= 1) mx = fmaxf(mx, __shfl_xor_sync(0xffffffffu, mx, o));
    if ((tid & 31) == 0) sh[tid >> 5] = mx;
    __syncthreads();
    mx = sh[0];
    #pragma unroll
    for (int w = 1; w < 8; w++) mx = fmaxf(mx, sh[w]);

    float sum = 0.f;
    #pragma unroll
    for (int i = 0; i < 4; i++) {
        v[i].x = expf(v[i].x - mx); v[i].y = expf(v[i].y - mx);
        v[i].z = expf(v[i].z - mx); v[i].w = expf(v[i].w - mx);
        sum += v[i].x + v[i].y + v[i].z + v[i].w;
    }
    #pragma unroll
    for (int o = 16; o; o >>= 1) sum += __shfl_xor_sync(0xffffffffu, sum, o);
    __syncthreads();
    if ((tid & 31) == 0) sh[tid >> 5] = sum;
    __syncthreads();
    sum = 0.f;
    #pragma unroll
    for (int w = 0; w < 8; w++) sum += sh[w];
    const float inv = 1.f / sum;
    #pragma unroll
    for (int i = 0; i < 4; i++) {
        v[i].x *= inv; v[i].y *= inv; v[i].z *= inv; v[i].w *= inv;
        ((float4*)p)[tid + i*256] = v[i];
    }
}

// ---------------------------------------------------------------------------
// launch
// ---------------------------------------------------------------------------
extern "C" void kernel_launch(void* const* d_in, const int* in_sizes, int n_in,
                              void* d_out, int out_size) {
    const float* x     = (const float*)d_in[0];
    const float* gamma = (const float*)d_in[1];
    const float* beta  = (const float*)d_in[2];
    const float* wq    = (const float*)d_in[3];
    const float* bq    = (const float*)d_in[4];
    const float* wk    = (const float*)d_in[5];
    const float* bk    = (const float*)d_in[6];
    const float* wv    = (const float*)d_in[7];
    const float* bv    = (const float*)d_in[8];
    const float* wp    = (const float*)d_in[9];
    const float* bp    = (const float*)d_in[10];
    float* out = (float*)d_out;

    float *xn, *qkv, *attn, *vt, *wt, *mean, *rstd;
    cudaGetSymbolAddress((void**)&xn,   g_xn);
    cudaGetSymbolAddress((void**)&qkv,  g_qkv);
    cudaGetSymbolAddress((void**)&attn, g_attn);
    cudaGetSymbolAddress((void**)&vt,   g_vt);
    cudaGetSymbolAddress((void**)&wt,   g_wt);
    cudaGetSymbolAddress((void**)&mean, g_mean);
    cudaGetSymbolAddress((void**)&rstd, g_rstd);
    float* q  = qkv;
    float* k  = qkv + (size_t)NBROWS*CD;
    float* v  = qkv + (size_t)2*NBROWS*CD;
    float* ao = xn;   // alias: xn dead after QKV projections
    float* wqT = wt;
    float* wkT = wt + (size_t)CD*CD;
    float* wvT = wt + (size_t)2*CD*CD;
    float* wpT = wt + (size_t)3*CD*CD;

    // 1) GroupNorm
    gn_stats<<<BSZ*NGROUPS, 256>>>(x, mean, rstd);
    gn_norm<<<(NBROWS*CD/4)/256, 256>>>(x, gamma, beta, mean, rstd, xn);

    // 2) weight transposes ([K,N] -> [N,K] so all GEMMs are NT)
    {
        dim3 b(32, 8), g(CD/32, CD/32, 1);
        transpose_kernel<<<g, b>>>(wq, wqT, CD, CD, 0, 0);
        transpose_kernel<<<g, b>>>(wk, wkT, CD, CD, 0, 0);
        transpose_kernel<<<g, b>>>(wv, wvT, CD, CD, 0, 0);
        transpose_kernel<<<g, b>>>(wp, wpT, CD, CD, 0, 0);
    }

    // 3) q, k, v projections: [8192,512] x [512,512]^T
    {
        dim3 g(CD/128, NBROWS/128, 1);
        gemm_mma<true, false><<<g, 256>>>(xn, wqT, bq, nullptr, q, CD, CD, CD, CD, 1.f, 0, 0, 0);
        gemm_mma<true, false><<<g, 256>>>(xn, wkT, bk, nullptr, k, CD, CD, CD, CD, 1.f, 0, 0, 0);
        gemm_mma<true, false><<<g, 256>>>(xn, wvT, bv, nullptr, v, CD, CD, CD, CD, 1.f, 0, 0, 0);
    }

    // 4) v transpose per batch: [4096,512] -> [512,4096]
    {
        dim3 b(32, 8), g(CD/32, HWN/32, BSZ);
        transpose_kernel<<<g, b>>>(v, vt, HWN, CD, (size_t)HWN*CD, (size_t)CD*HWN);
    }

    // 5) scores = q k^T * 1/sqrt(C)  (NT: both K-major), batches via z
    const float scale = 0.044194173824159216f;
    {
        dim3 g(HWN/128, HWN/128, BSZ);
        gemm_mma<false, false><<<g, 256>>>(q, k, nullptr, nullptr, attn,
                                           CD, CD, CD, HWN, scale,
                                           (size_t)HWN*CD, (size_t)HWN*CD, (size_t)HWN*HWN);
    }

    // 6) softmax rows (in place)
    softmax_kernel<<<NBROWS, 256>>>(attn);

    // 7) ao = attn @ v  (NT with vT: K=4096), batches via z
    {
        dim3 g(CD/128, HWN/128, BSZ);
        gemm_mma<false, false><<<g, 256>>>(attn, vt, nullptr, nullptr, ao,
                                           HWN, HWN, HWN, CD, 1.f,
                                           (size_t)HWN*HWN, (size_t)CD*HWN, (size_t)HWN*CD);
    }

    // 8) final projection + bias + residual -> d_out
    {
        dim3 g(CD/128, NBROWS/128, 1);
        gemm_mma<true, true><<<g, 256>>>(ao, wpT, bp, x, out, CD, CD, CD, CD, 1.f, 0, 0, 0);
    }
}

// round 12
// speedup vs baseline: 1.1880x; 1.1880x over previous
#include <cuda_runtime.h>
#include <cuda_fp16.h>
#include <math.h>
#include <stdint.h>

// Problem constants (fixed shapes)
#define BSZ 2
#define HWN 4096
#define CD  512
#define NBROWS (BSZ*HWN)      // 8192
#define NGROUPS 32

// ---------------------------------------------------------------------------
// Scratch (device globals; no allocations)
// ---------------------------------------------------------------------------
__device__ __half g_xn16 [(size_t)NBROWS*CD];
__device__ __half g_qkv16[(size_t)3*NBROWS*CD];        // q16 | k16 | v16
__device__ __half g_wt16 [(size_t)4*CD*CD];            // wqT|wkT|wvT|wpT (half)
__device__ __half g_vt16 [(size_t)BSZ*CD*HWN];         // v transposed per batch
__device__ float  g_attn [(size_t)BSZ*HWN*HWN];        // raw scores fp32 (134 MB)
__device__ __half g_attn16[(size_t)BSZ*HWN*HWN];       // softmax weights fp16 (67 MB)
__device__ __half g_ao16 [(size_t)NBROWS*CD];
__device__ float  g_b3   [3*CD];                       // bq|bk|bv packed
__device__ float  g_mean [BSZ*NGROUPS];
__device__ float  g_rstd [BSZ*NGROUPS];

// ---------------------------------------------------------------------------
// helpers
// ---------------------------------------------------------------------------
__device__ __forceinline__ uint32_t smem_u32(const void* p) {
    uint32_t a;
    asm("{ .reg .u64 t; cvta.to.shared.u64 t, %1; cvt.u32.u64 %0, t; }" : "=r"(a) : "l"(p));
    return a;
}
__device__ __forceinline__ void cp16(uint32_t dst, const void* src) {
    asm volatile("cp.async.cg.shared.global [%0], [%1], 16;" :: "r"(dst), "l"(src));
}
#define CP_COMMIT() asm volatile("cp.async.commit_group;")
#define CP_WAIT1()  asm volatile("cp.async.wait_group 1;")

__device__ __forceinline__ void mma_f16(float c[4], const uint32_t a[4], const uint32_t b[2]) {
    asm volatile(
        "mma.sync.aligned.m16n8k16.row.col.f32.f16.f16.f32 "
        "{%0,%1,%2,%3}, {%4,%5,%6,%7}, {%8,%9}, {%0,%1,%2,%3};"
        : "+f"(c[0]), "+f"(c[1]), "+f"(c[2]), "+f"(c[3])
        : "r"(a[0]), "r"(a[1]), "r"(a[2]), "r"(a[3]), "r"(b[0]), "r"(b[1]));
}

// ---------------------------------------------------------------------------
// GroupNorm stats (+ fused bias pack in block 64)
// ---------------------------------------------------------------------------
__global__ void gn_stats_bias(const float* __restrict__ x,
                              float* __restrict__ mean, float* __restrict__ rstd,
                              const float* __restrict__ bq, const float* __restrict__ bk,
                              const float* __restrict__ bv, float* __restrict__ b3) {
    if (blockIdx.x == 64) {
        for (int i = threadIdx.x; i < CD; i += 256) {
            b3[i] = bq[i]; b3[CD + i] = bk[i]; b3[2*CD + i] = bv[i];
        }
        return;
    }
    __shared__ float shs[8], shss[8];
    const int bg = blockIdx.x;
    const int b = bg >> 5, g = bg & 31;
    const float4* xb = (const float4*)x + (size_t)b*524288 + g*4;
    float s = 0.f, ss = 0.f;
    for (int i = threadIdx.x; i < 16384; i += 256) {
        int n = i >> 2, j = i & 3;
        float4 vv = xb[(size_t)n*128 + j];
        s  += vv.x + vv.y + vv.z + vv.w;
        ss += vv.x*vv.x + vv.y*vv.y + vv.z*vv.z + vv.w*vv.w;
    }
    #pragma unroll
    for (int o = 16; o; o >>= 1) {
        s  += __shfl_xor_sync(0xffffffffu, s,  o);
        ss += __shfl_xor_sync(0xffffffffu, ss, o);
    }
    if ((threadIdx.x & 31) == 0) { shs[threadIdx.x>>5] = s; shss[threadIdx.x>>5] = ss; }
    __syncthreads();
    if (threadIdx.x == 0) {
        s = 0.f; ss = 0.f;
        #pragma unroll
        for (int w = 0; w < 8; w++) { s += shs[w]; ss += shss[w]; }
        float m   = s * (1.f/65536.f);
        float var = ss * (1.f/65536.f) - m*m;
        mean[bg] = m;
        rstd[bg] = rsqrtf(var + 1e-5f);
    }
}

// GroupNorm normalize -> fp16 output
__global__ void gn_norm(const float* __restrict__ x,
                        const float* __restrict__ gamma, const float* __restrict__ beta,
                        const float* __restrict__ mean, const float* __restrict__ rstd,
                        __half* __restrict__ xn) {
    const int idx = blockIdx.x * blockDim.x + threadIdx.x;   // float4 index
    float4 v = ((const float4*)x)[idx];
    const int c4 = idx & 127;
    const int b  = idx >> 19;
    const int g  = c4 >> 2;
    const int bg = b * 32 + g;
    const float m = mean[bg], r = rstd[bg];
    const float4 ga = ((const float4*)gamma)[c4];
    const float4 be = ((const float4*)beta)[c4];
    __half2 h0 = __float22half2_rn(make_float2((v.x - m)*r*ga.x + be.x, (v.y - m)*r*ga.y + be.y));
    __half2 h1 = __float22half2_rn(make_float2((v.z - m)*r*ga.z + be.z, (v.w - m)*r*ga.w + be.w));
    uint2 o = make_uint2(*(uint32_t*)&h0, *(uint32_t*)&h1);
    ((uint2*)xn)[idx] = o;
}

// 4 weight transposes fused (z selects weight), fp32 in -> fp16 out
__global__ void wtrans4(const float* __restrict__ w0, const float* __restrict__ w1,
                        const float* __restrict__ w2, const float* __restrict__ w3,
                        __half* __restrict__ out) {
    __shared__ float t[32][33];
    const float* src = blockIdx.z == 0 ? w0 : blockIdx.z == 1 ? w1 : blockIdx.z == 2 ? w2 : w3;
    __half* dst = out + (size_t)blockIdx.z * CD * CD;
    int c0 = blockIdx.x * 32, r0 = blockIdx.y * 32;
    int xx = threadIdx.x;
    #pragma unroll
    for (int y = threadIdx.y; y < 32; y += 8)
        t[y][xx] = src[(size_t)(r0 + y) * CD + c0 + xx];
    __syncthreads();
    #pragma unroll
    for (int y = threadIdx.y; y < 32; y += 8)
        dst[(size_t)(c0 + y) * CD + r0 + xx] = __float2half_rn(t[xx][y]);
}

// v16 [b][n][c] -> vt16 [b][c][n]
__global__ void vtrans_h(const __half* __restrict__ in, __half* __restrict__ out) {
    __shared__ __half t[32][33];
    const __half* inz = in + (size_t)blockIdx.z * HWN * CD;
    __half* outz = out + (size_t)blockIdx.z * CD * HWN;
    int c0 = blockIdx.x * 32, r0 = blockIdx.y * 32;
    int xx = threadIdx.x;
    #pragma unroll
    for (int y = threadIdx.y; y < 32; y += 8)
        t[y][xx] = inz[(size_t)(r0 + y) * CD + c0 + xx];
    __syncthreads();
    #pragma unroll
    for (int y = threadIdx.y; y < 32; y += 8)
        outz[(size_t)(c0 + y) * HWN + r0 + xx] = t[xx][y];
}

// ---------------------------------------------------------------------------
// fp16-input NT GEMM, cp.async 3-stage pipeline:
//   C[m][n] = alpha * sum_k A[m][k]*Bt[n][k]  (+bias[n]) (+res[m][n])
// CTA 128x128, BK=16, 256 thr = 8 warps (2m x 4n), warp tile 64x32.
// SMEM rows: 8 half2 words + 4 pad (SMS=12) -> conflict-free fragment LDS.
// HOUT: write __half2, else float2 (+res fp32).
// ---------------------------------------------------------------------------
#define SMS 12
#define STAGE_WORDS (128 * SMS)

template<bool BIAS, bool RES, bool HOUT>
__global__ __launch_bounds__(256)
void gemm_h(const __half* __restrict__ A, const __half* __restrict__ Bt,
            const float* __restrict__ bias, const float* __restrict__ res,
            void* __restrict__ Cptr,
            int K, int lda, int ldb, int ldc, float alpha,
            size_t zA, size_t zB, size_t zC, size_t zBias) {
    __shared__ uint32_t As[3][STAGE_WORDS];
    __shared__ uint32_t Bs[3][STAGE_WORDS];

    A  += blockIdx.z * zA;
    Bt += blockIdx.z * zB;
    const float* biasz = BIAS ? (bias + blockIdx.z * zBias) : bias;
    float*  Cf = (float*)Cptr  + (HOUT ? 0 : blockIdx.z * zC);
    __half* Ch = (__half*)Cptr + (HOUT ? blockIdx.z * zC : 0);

    const int tid = threadIdx.x;
    const int wid = tid >> 5;
    const int lane = tid & 31;
    const int gid = lane >> 2;
    const int tg  = lane & 3;
    const int wm = (wid & 1) * 64;
    const int wn = (wid >> 1) * 32;
    const int rowBlock = blockIdx.y * 128;
    const int colBlock = blockIdx.x * 128;

    // staging: thread owns one 16B chunk of one row for A and one for B
    const int srow   = tid >> 1;        // 0..127
    const int schunk = tid & 1;         // 0..1 (16B halves of the 32B row)
    const __half* Asrc = A  + (size_t)(rowBlock + srow) * lda + schunk * 8;
    const __half* Bsrc = Bt + (size_t)(colBlock + srow) * ldb + schunk * 8;
    const uint32_t aDst = smem_u32(&As[0][0]) + srow * (SMS*4) + schunk * 16;
    const uint32_t bDst = smem_u32(&Bs[0][0]) + srow * (SMS*4) + schunk * 16;
    const uint32_t stageB = STAGE_WORDS * 4;

    float acc[4][4][4];
    #pragma unroll
    for (int mi = 0; mi < 4; mi++)
        #pragma unroll
        for (int ni = 0; ni < 4; ni++)
            #pragma unroll
            for (int r = 0; r < 4; r++) acc[mi][ni][r] = 0.f;

    const int T = K >> 4;

    // prologue: stage tiles 0 and 1
    cp16(aDst,          Asrc);
    cp16(bDst,          Bsrc);
    CP_COMMIT();
    cp16(aDst + stageB, Asrc + 16);
    cp16(bDst + stageB, Bsrc + 16);
    CP_COMMIT();

    int s = 0;
    for (int t = 0; t < T; t++) {
        CP_WAIT1();
        __syncthreads();

        // issue tile t+2 into stage (s+2)%3 (overlaps with compute below)
        if (t + 2 < T) {
            const int s2 = (s + 2 >= 3) ? s - 1 : s + 2;
            cp16(aDst + s2 * stageB, Asrc + (size_t)(t + 2) * 16);
            cp16(bDst + s2 * stageB, Bsrc + (size_t)(t + 2) * 16);
        }
        CP_COMMIT();   // always commit to keep group count aligned

        const uint32_t* Ab = As[s];
        const uint32_t* Bb = Bs[s];
        uint32_t af[4][4];
        #pragma unroll
        for (int mi = 0; mi < 4; mi++) {
            const int base = (wm + mi * 16 + gid) * SMS;
            af[mi][0] = Ab[base + tg];
            af[mi][1] = Ab[base + 8 * SMS + tg];
            af[mi][2] = Ab[base + tg + 4];
            af[mi][3] = Ab[base + 8 * SMS + tg + 4];
        }
        uint32_t bf[4][2];
        #pragma unroll
        for (int ni = 0; ni < 4; ni++) {
            const int base = (wn + ni * 8 + gid) * SMS;
            bf[ni][0] = Bb[base + tg];
            bf[ni][1] = Bb[base + tg + 4];
        }
        #pragma unroll
        for (int mi = 0; mi < 4; mi++)
            #pragma unroll
            for (int ni = 0; ni < 4; ni++)
                mma_f16(acc[mi][ni], af[mi], bf[ni]);

        s = (s + 1 == 3) ? 0 : s + 1;
    }

    // epilogue
    #pragma unroll
    for (int mi = 0; mi < 4; mi++) {
        #pragma unroll
        for (int half = 0; half < 2; half++) {
            const size_t r = (size_t)(rowBlock + wm + mi * 16 + gid + half * 8);
            #pragma unroll
            for (int ni = 0; ni < 4; ni++) {
                const size_t c = (size_t)(colBlock + wn + ni * 8 + 2 * tg);
                float ox = acc[mi][ni][half * 2 + 0] * alpha;
                float oy = acc[mi][ni][half * 2 + 1] * alpha;
                if (BIAS) {
                    const float2 bb = *(const float2*)(biasz + c);
                    ox += bb.x; oy += bb.y;
                }
                if (RES) {
                    const float2 rr = *(const float2*)(res + r * ldc + c);
                    ox += rr.x; oy += rr.y;
                }
                if (HOUT) {
                    __half2 h = __float22half2_rn(make_float2(ox, oy));
                    *(__half2*)(Ch + r * ldc + c) = h;
                } else {
                    *(float2*)(Cf + r * ldc + c) = make_float2(ox, oy);
                }
            }
        }
    }
}

// ---------------------------------------------------------------------------
// Row softmax: fp32 scores in, fp16 weights out
// ---------------------------------------------------------------------------
__global__ void softmax_h(const float* __restrict__ S, __half* __restrict__ O) {
    __shared__ float sh[8];
    const size_t row = blockIdx.x;
    const float* p = S + row * 4096;
    __half* po = O + row * 4096;
    const int tid = threadIdx.x;
    float4 v[4];
    float mx = -1e30f;
    #pragma unroll
    for (int i = 0; i < 4; i++) {
        v[i] = ((const float4*)p)[tid + i*256];
        mx = fmaxf(mx, fmaxf(fmaxf(v[i].x, v[i].y), fmaxf(v[i].z, v[i].w)));
    }
    #pragma unroll
    for (int o = 16; o; o >>= 1) mx = fmaxf(mx, __shfl_xor_sync(0xffffffffu, mx, o));
    if ((tid & 31) == 0) sh[tid >> 5] = mx;
    __syncthreads();
    mx = sh[0];
    #pragma unroll
    for (int w = 1; w < 8; w++) mx = fmaxf(mx, sh[w]);

    float sum = 0.f;
    #pragma unroll
    for (int i = 0; i < 4; i++) {
        v[i].x = expf(v[i].x - mx); v[i].y = expf(v[i].y - mx);
        v[i].z = expf(v[i].z - mx); v[i].w = expf(v[i].w - mx);
        sum += v[i].x + v[i].y + v[i].z + v[i].w;
    }
    #pragma unroll
    for (int o = 16; o; o >>= 1) sum += __shfl_xor_sync(0xffffffffu, sum, o);
    __syncthreads();
    if ((tid & 31) == 0) sh[tid >> 5] = sum;
    __syncthreads();
    sum = 0.f;
    #pragma unroll
    for (int w = 0; w < 8; w++) sum += sh[w];
    const float inv = 1.f / sum;
    #pragma unroll
    for (int i = 0; i < 4; i++) {
        __half2 h0 = __float22half2_rn(make_float2(v[i].x * inv, v[i].y * inv));
        __half2 h1 = __float22half2_rn(make_float2(v[i].z * inv, v[i].w * inv));
        ((uint2*)po)[tid + i*256] = make_uint2(*(uint32_t*)&h0, *(uint32_t*)&h1);
    }
}

// ---------------------------------------------------------------------------
// launch
// ---------------------------------------------------------------------------
extern "C" void kernel_launch(void* const* d_in, const int* in_sizes, int n_in,
                              void* d_out, int out_size) {
    const float* x     = (const float*)d_in[0];
    const float* gamma = (const float*)d_in[1];
    const float* beta  = (const float*)d_in[2];
    const float* wq    = (const float*)d_in[3];
    const float* bq    = (const float*)d_in[4];
    const float* wk    = (const float*)d_in[5];
    const float* bk    = (const float*)d_in[6];
    const float* wv    = (const float*)d_in[7];
    const float* bv    = (const float*)d_in[8];
    const float* wp    = (const float*)d_in[9];
    const float* bp    = (const float*)d_in[10];
    float* out = (float*)d_out;

    __half *xn16, *qkv16, *wt16, *vt16, *attn16, *ao16;
    float *attnF, *b3, *mean, *rstd;
    cudaGetSymbolAddress((void**)&xn16,   g_xn16);
    cudaGetSymbolAddress((void**)&qkv16,  g_qkv16);
    cudaGetSymbolAddress((void**)&wt16,   g_wt16);
    cudaGetSymbolAddress((void**)&vt16,   g_vt16);
    cudaGetSymbolAddress((void**)&attnF,  g_attn);
    cudaGetSymbolAddress((void**)&attn16, g_attn16);
    cudaGetSymbolAddress((void**)&ao16,   g_ao16);
    cudaGetSymbolAddress((void**)&b3,     g_b3);
    cudaGetSymbolAddress((void**)&mean,   g_mean);
    cudaGetSymbolAddress((void**)&rstd,   g_rstd);
    __half* q16 = qkv16;
    __half* k16 = qkv16 + (size_t)NBROWS*CD;
    __half* v16 = qkv16 + (size_t)2*NBROWS*CD;
    __half* wpT16 = wt16 + (size_t)3*CD*CD;

    // 1) GroupNorm stats + bias pack
    gn_stats_bias<<<65, 256>>>(x, mean, rstd, bq, bk, bv, b3);

    // 2) normalize -> fp16
    gn_norm<<<(NBROWS*CD/4)/256, 256>>>(x, gamma, beta, mean, rstd, xn16);

    // 3) weight transposes (fused, z=4) -> fp16
    wtrans4<<<dim3(CD/32, CD/32, 4), dim3(32, 8)>>>(wq, wk, wv, wp, wt16);

    // 4) fused qkv projections: z selects (wT, bias, out slab)
    gemm_h<true, false, true><<<dim3(CD/128, NBROWS/128, 3), 256>>>(
        xn16, wt16, b3, nullptr, qkv16, CD, CD, CD, CD, 1.f,
        0, (size_t)CD*CD, (size_t)NBROWS*CD, (size_t)CD);

    // 5) scores = q k^T * 1/sqrt(C) -> fp32 (likely the profiled launch)
    const float scale = 0.044194173824159216f;
    gemm_h<false, false, false><<<dim3(HWN/128, HWN/128, BSZ), 256>>>(
        q16, k16, nullptr, nullptr, attnF, CD, CD, CD, HWN, scale,
        (size_t)HWN*CD, (size_t)HWN*CD, (size_t)HWN*HWN, 0);

    // 6) v transpose per batch (half)
    vtrans_h<<<dim3(CD/32, HWN/32, BSZ), dim3(32, 8)>>>(v16, vt16);

    // 7) softmax: fp32 in -> fp16 weights
    softmax_h<<<NBROWS, 256>>>(attnF, attn16);

    // 8) ao = attn @ v (K=4096, all-half inputs) -> fp16
    gemm_h<false, false, true><<<dim3(CD/128, HWN/128, BSZ), 256>>>(
        attn16, vt16, nullptr, nullptr, ao16, HWN, HWN, HWN, CD, 1.f,
        (size_t)HWN*HWN, (size_t)CD*HWN, (size_t)HWN*CD, 0);

    // 9) final projection + bias + residual -> fp32 d_out
    gemm_h<true, true, false><<<dim3(CD/128, NBROWS/128, 1), 256>>>(
        ao16, wpT16, bp, x, out, CD, CD, CD, CD, 1.f, 0, 0, 0, 0);
}

// round 13
// speedup vs baseline: 2.6348x; 2.2179x over previous
#include <cuda_runtime.h>
#include <cuda_fp16.h>
#include <math.h>
#include <stdint.h>

// Problem constants (fixed shapes)
#define BSZ 2
#define HWN 4096
#define CD  512
#define NBROWS (BSZ*HWN)      // 8192
#define NGROUPS 32

// ---------------------------------------------------------------------------
// Scratch (device globals; no allocations)
// ---------------------------------------------------------------------------
__device__ __half g_xn16 [(size_t)NBROWS*CD];
__device__ __half g_qkv16[(size_t)3*NBROWS*CD];        // q16 | k16 | v16
__device__ __half g_wt16 [(size_t)4*CD*CD];            // wqT|wkT|wvT|wpT (half)
__device__ __half g_vt16 [(size_t)BSZ*CD*HWN];         // v transposed per batch
__device__ float  g_attn [(size_t)BSZ*HWN*HWN];        // raw scores fp32 (134 MB)
__device__ __half g_attn16[(size_t)BSZ*HWN*HWN];       // softmax weights fp16 (67 MB)
__device__ __half g_ao16 [(size_t)NBROWS*CD];
__device__ float  g_b3   [3*CD];                       // bq|bk|bv packed
__device__ float  g_mean [BSZ*NGROUPS];
__device__ float  g_rstd [BSZ*NGROUPS];

// ---------------------------------------------------------------------------
// helpers
// ---------------------------------------------------------------------------
__device__ __forceinline__ uint32_t smem_u32(const void* p) {
    uint32_t a;
    asm("{ .reg .u64 t; cvta.to.shared.u64 t, %1; cvt.u32.u64 %0, t; }" : "=r"(a) : "l"(p));
    return a;
}
__device__ __forceinline__ void cp16(uint32_t dst, const void* src) {
    asm volatile("cp.async.cg.shared.global [%0], [%1], 16;" :: "r"(dst), "l"(src));
}
#define CP_COMMIT() asm volatile("cp.async.commit_group;")
#define CP_WAIT1()  asm volatile("cp.async.wait_group 1;")

__device__ __forceinline__ void ldmx4(uint32_t r[4], uint32_t addr) {
    asm volatile("ldmatrix.sync.aligned.m8n8.x4.shared.b16 {%0,%1,%2,%3}, [%4];"
        : "=r"(r[0]), "=r"(r[1]), "=r"(r[2]), "=r"(r[3]) : "r"(addr));
}
__device__ __forceinline__ void mma_f16(float c[4], const uint32_t a[4], const uint32_t b[2]) {
    asm volatile(
        "mma.sync.aligned.m16n8k16.row.col.f32.f16.f16.f32 "
        "{%0,%1,%2,%3}, {%4,%5,%6,%7}, {%8,%9}, {%0,%1,%2,%3};"
        : "+f"(c[0]), "+f"(c[1]), "+f"(c[2]), "+f"(c[3])
        : "r"(a[0]), "r"(a[1]), "r"(a[2]), "r"(a[3]), "r"(b[0]), "r"(b[1]));
}

// ---------------------------------------------------------------------------
// GroupNorm stats (+ fused bias pack in block 64)
// ---------------------------------------------------------------------------
__global__ void gn_stats_bias(const float* __restrict__ x,
                              float* __restrict__ mean, float* __restrict__ rstd,
                              const float* __restrict__ bq, const float* __restrict__ bk,
                              const float* __restrict__ bv, float* __restrict__ b3) {
    if (blockIdx.x == 64) {
        for (int i = threadIdx.x; i < CD; i += 256) {
            b3[i] = bq[i]; b3[CD + i] = bk[i]; b3[2*CD + i] = bv[i];
        }
        return;
    }
    __shared__ float shs[8], shss[8];
    const int bg = blockIdx.x;
    const int b = bg >> 5, g = bg & 31;
    const float4* xb = (const float4*)x + (size_t)b*524288 + g*4;
    float s = 0.f, ss = 0.f;
    for (int i = threadIdx.x; i < 16384; i += 256) {
        int n = i >> 2, j = i & 3;
        float4 vv = xb[(size_t)n*128 + j];
        s  += vv.x + vv.y + vv.z + vv.w;
        ss += vv.x*vv.x + vv.y*vv.y + vv.z*vv.z + vv.w*vv.w;
    }
    #pragma unroll
    for (int o = 16; o; o >>= 1) {
        s  += __shfl_xor_sync(0xffffffffu, s,  o);
        ss += __shfl_xor_sync(0xffffffffu, ss, o);
    }
    if ((threadIdx.x & 31) == 0) { shs[threadIdx.x>>5] = s; shss[threadIdx.x>>5] = ss; }
    __syncthreads();
    if (threadIdx.x == 0) {
        s = 0.f; ss = 0.f;
        #pragma unroll
        for (int w = 0; w < 8; w++) { s += shs[w]; ss += shss[w]; }
        float m   = s * (1.f/65536.f);
        float var = ss * (1.f/65536.f) - m*m;
        mean[bg] = m;
        rstd[bg] = rsqrtf(var + 1e-5f);
    }
}

// GroupNorm normalize -> fp16 output
__global__ void gn_norm(const float* __restrict__ x,
                        const float* __restrict__ gamma, const float* __restrict__ beta,
                        const float* __restrict__ mean, const float* __restrict__ rstd,
                        __half* __restrict__ xn) {
    const int idx = blockIdx.x * blockDim.x + threadIdx.x;   // float4 index
    float4 v = ((const float4*)x)[idx];
    const int c4 = idx & 127;
    const int b  = idx >> 19;
    const int g  = c4 >> 2;
    const int bg = b * 32 + g;
    const float m = mean[bg], r = rstd[bg];
    const float4 ga = ((const float4*)gamma)[c4];
    const float4 be = ((const float4*)beta)[c4];
    __half2 h0 = __float22half2_rn(make_float2((v.x - m)*r*ga.x + be.x, (v.y - m)*r*ga.y + be.y));
    __half2 h1 = __float22half2_rn(make_float2((v.z - m)*r*ga.z + be.z, (v.w - m)*r*ga.w + be.w));
    uint2 o = make_uint2(*(uint32_t*)&h0, *(uint32_t*)&h1);
    ((uint2*)xn)[idx] = o;
}

// 4 weight transposes fused (z selects weight), fp32 in -> fp16 out
__global__ void wtrans4(const float* __restrict__ w0, const float* __restrict__ w1,
                        const float* __restrict__ w2, const float* __restrict__ w3,
                        __half* __restrict__ out) {
    __shared__ float t[32][33];
    const float* src = blockIdx.z == 0 ? w0 : blockIdx.z == 1 ? w1 : blockIdx.z == 2 ? w2 : w3;
    __half* dst = out + (size_t)blockIdx.z * CD * CD;
    int c0 = blockIdx.x * 32, r0 = blockIdx.y * 32;
    int xx = threadIdx.x;
    #pragma unroll
    for (int y = threadIdx.y; y < 32; y += 8)
        t[y][xx] = src[(size_t)(r0 + y) * CD + c0 + xx];
    __syncthreads();
    #pragma unroll
    for (int y = threadIdx.y; y < 32; y += 8)
        dst[(size_t)(c0 + y) * CD + r0 + xx] = __float2half_rn(t[xx][y]);
}

// v16 [b][n][c] -> vt16 [b][c][n]
__global__ void vtrans_h(const __half* __restrict__ in, __half* __restrict__ out) {
    __shared__ __half t[32][33];
    const __half* inz = in + (size_t)blockIdx.z * HWN * CD;
    __half* outz = out + (size_t)blockIdx.z * CD * HWN;
    int c0 = blockIdx.x * 32, r0 = blockIdx.y * 32;
    int xx = threadIdx.x;
    #pragma unroll
    for (int y = threadIdx.y; y < 32; y += 8)
        t[y][xx] = inz[(size_t)(r0 + y) * CD + c0 + xx];
    __syncthreads();
    #pragma unroll
    for (int y = threadIdx.y; y < 32; y += 8)
        outz[(size_t)(c0 + y) * HWN + r0 + xx] = t[xx][y];
}

// ---------------------------------------------------------------------------
// fp16 NT GEMM, cp.async 3-stage + ldmatrix fragments + XOR-swizzled SMEM:
//   C[m][n] = alpha * sum_k A[m][k]*Bt[n][k]  (+bias[n]) (+res[m][n])
// CTA 128x128, BK=32 (2 k16 steps), 256 thr = 8 warps (2m x 4n), warp 64x32.
// SMEM rows 64B (32 half); 16B chunk c stored at c ^ ((row>>1)&3) ->
// conflict-free ldmatrix (each 8-addr round covers all 32 banks).
// ---------------------------------------------------------------------------
#define STAGE_U32 2048          // 8 KB per operand per stage
#define STAGE_BYTES 8192

template<bool BIAS, bool RES, bool HOUT>
__global__ __launch_bounds__(256)
void gemm_h(const __half* __restrict__ A, const __half* __restrict__ Bt,
            const float* __restrict__ bias, const float* __restrict__ res,
            void* __restrict__ Cptr,
            int K, int lda, int ldb, int ldc, float alpha,
            size_t zA, size_t zB, size_t zC, size_t zBias) {
    __shared__ uint32_t As[3][STAGE_U32];
    __shared__ uint32_t Bs[3][STAGE_U32];

    A  += blockIdx.z * zA;
    Bt += blockIdx.z * zB;
    const float* biasz = BIAS ? (bias + blockIdx.z * zBias) : bias;
    float*  Cf = (float*)Cptr  + (HOUT ? 0 : blockIdx.z * zC);
    __half* Ch = (__half*)Cptr + (HOUT ? blockIdx.z * zC : 0);

    const int tid = threadIdx.x;
    const int wid = tid >> 5;
    const int lane = tid & 31;
    const int gid = lane >> 2;
    const int tg  = lane & 3;
    const int wm = (wid & 1) * 64;
    const int wn = (wid >> 1) * 32;
    const int rowBlock = blockIdx.y * 128;
    const int colBlock = blockIdx.x * 128;

    // ---- cp.async staging coords: chunk id = tid (row=tid>>2, c=tid&3) and +256
    const int srow = tid >> 2;          // 0..63
    const int sc   = tid & 3;           // 16B chunk in row
    const uint32_t sdst = (uint32_t)srow * 64 + (uint32_t)((sc ^ ((srow >> 1) & 3)) * 16);
    const __half* Asrc = A  + (size_t)(rowBlock + srow) * lda + sc * 8;
    const __half* Bsrc = Bt + (size_t)(colBlock + srow) * ldb + sc * 8;
    const uint32_t aS = smem_u32(&As[0][0]);
    const uint32_t bS = smem_u32(&Bs[0][0]);
    // rows +64 share the same swizzle value -> dst offset +4096
    const size_t aRow64 = (size_t)64 * lda;
    const size_t bRow64 = (size_t)64 * ldb;

    // ---- ldmatrix per-lane fragment addresses
    const int rowA = wm + ((lane >> 3) & 1) * 8 + (lane & 7);
    const uint32_t offA = (uint32_t)rowA * 64 +
                          (uint32_t)(((( lane >> 4) & 1) ^ ((rowA >> 1) & 3)) * 16);
    const int rowB = wn + ((lane >> 4) & 1) * 8 + (lane & 7);
    const uint32_t offB = (uint32_t)rowB * 64 +
                          (uint32_t)(((( lane >> 3) & 1) ^ ((rowB >> 1) & 3)) * 16);

    float acc[4][4][4];
    #pragma unroll
    for (int mi = 0; mi < 4; mi++)
        #pragma unroll
        for (int ni = 0; ni < 4; ni++)
            #pragma unroll
            for (int r = 0; r < 4; r++) acc[mi][ni][r] = 0.f;

    const int T = K >> 5;     // BK=32 tiles

    // prologue: stage tiles 0 and 1
    #pragma unroll
    for (int st = 0; st < 2; st++) {
        cp16(aS + st * STAGE_BYTES + sdst,        Asrc + st * 32);
        cp16(aS + st * STAGE_BYTES + sdst + 4096, Asrc + aRow64 + st * 32);
        cp16(bS + st * STAGE_BYTES + sdst,        Bsrc + st * 32);
        cp16(bS + st * STAGE_BYTES + sdst + 4096, Bsrc + bRow64 + st * 32);
        CP_COMMIT();
    }

    int s = 0;
    for (int t = 0; t < T; t++) {
        CP_WAIT1();
        __syncthreads();

        if (t + 2 < T) {
            int s2 = s + 2; if (s2 >= 3) s2 -= 3;
            const int kh = (t + 2) * 32;     // halves
            cp16(aS + s2 * STAGE_BYTES + sdst,        Asrc + kh);
            cp16(aS + s2 * STAGE_BYTES + sdst + 4096, Asrc + aRow64 + kh);
            cp16(bS + s2 * STAGE_BYTES + sdst,        Bsrc + kh);
            cp16(bS + s2 * STAGE_BYTES + sdst + 4096, Bsrc + bRow64 + kh);
        }
        CP_COMMIT();

        const uint32_t aBase = aS + s * STAGE_BYTES;
        const uint32_t bBase = bS + s * STAGE_BYTES;
        #pragma unroll
        for (int ks = 0; ks < 2; ks++) {
            uint32_t af[4][4], bf[2][4];
            #pragma unroll
            for (int mi = 0; mi < 4; mi++)
                ldmx4(af[mi], aBase + mi * 1024 + (offA ^ (ks << 5)));
            #pragma unroll
            for (int p = 0; p < 2; p++)
                ldmx4(bf[p], bBase + p * 1024 + (offB ^ (ks << 5)));
            #pragma unroll
            for (int mi = 0; mi < 4; mi++)
                #pragma unroll
                for (int ni = 0; ni < 4; ni++)
                    mma_f16(acc[mi][ni], af[mi], &bf[ni >> 1][(ni & 1) * 2]);
        }

        s++; if (s == 3) s = 0;
    }

    // epilogue (fragment layout identical to validated scalar version)
    #pragma unroll
    for (int mi = 0; mi < 4; mi++) {
        #pragma unroll
        for (int half = 0; half < 2; half++) {
            const size_t r = (size_t)(rowBlock + wm + mi * 16 + gid + half * 8);
            #pragma unroll
            for (int ni = 0; ni < 4; ni++) {
                const size_t c = (size_t)(colBlock + wn + ni * 8 + 2 * tg);
                float ox = acc[mi][ni][half * 2 + 0] * alpha;
                float oy = acc[mi][ni][half * 2 + 1] * alpha;
                if (BIAS) {
                    const float2 bb = *(const float2*)(biasz + c);
                    ox += bb.x; oy += bb.y;
                }
                if (RES) {
                    const float2 rr = *(const float2*)(res + r * ldc + c);
                    ox += rr.x; oy += rr.y;
                }
                if (HOUT) {
                    __half2 h = __float22half2_rn(make_float2(ox, oy));
                    *(__half2*)(Ch + r * ldc + c) = h;
                } else {
                    *(float2*)(Cf + r * ldc + c) = make_float2(ox, oy);
                }
            }
        }
    }
}

// ---------------------------------------------------------------------------
// Row softmax: fp32 scores in, fp16 weights out
// ---------------------------------------------------------------------------
__global__ void softmax_h(const float* __restrict__ S, __half* __restrict__ O) {
    __shared__ float sh[8];
    const size_t row = blockIdx.x;
    const float* p = S + row * 4096;
    __half* po = O + row * 4096;
    const int tid = threadIdx.x;
    float4 v[4];
    float mx = -1e30f;
    #pragma unroll
    for (int i = 0; i < 4; i++) {
        v[i] = ((const float4*)p)[tid + i*256];
        mx = fmaxf(mx, fmaxf(fmaxf(v[i].x, v[i].y), fmaxf(v[i].z, v[i].w)));
    }
    #pragma unroll
    for (int o = 16; o; o >>= 1) mx = fmaxf(mx, __shfl_xor_sync(0xffffffffu, mx, o));
    if ((tid & 31) == 0) sh[tid >> 5] = mx;
    __syncthreads();
    mx = sh[0];
    #pragma unroll
    for (int w = 1; w < 8; w++) mx = fmaxf(mx, sh[w]);

    float sum = 0.f;
    #pragma unroll
    for (int i = 0; i < 4; i++) {
        v[i].x = expf(v[i].x - mx); v[i].y = expf(v[i].y - mx);
        v[i].z = expf(v[i].z - mx); v[i].w = expf(v[i].w - mx);
        sum += v[i].x + v[i].y + v[i].z + v[i].w;
    }
    #pragma unroll
    for (int o = 16; o; o >>= 1) sum += __shfl_xor_sync(0xffffffffu, sum, o);
    __syncthreads();
    if ((tid & 31) == 0) sh[tid >> 5] = sum;
    __syncthreads();
    sum = 0.f;
    #pragma unroll
    for (int w = 0; w < 8; w++) sum += sh[w];
    const float inv = 1.f / sum;
    #pragma unroll
    for (int i = 0; i < 4; i++) {
        __half2 h0 = __float22half2_rn(make_float2(v[i].x * inv, v[i].y * inv));
        __half2 h1 = __float22half2_rn(make_float2(v[i].z * inv, v[i].w * inv));
        ((uint2*)po)[tid + i*256] = make_uint2(*(uint32_t*)&h0, *(uint32_t*)&h1);
    }
}

// ---------------------------------------------------------------------------
// launch
// ---------------------------------------------------------------------------
extern "C" void kernel_launch(void* const* d_in, const int* in_sizes, int n_in,
                              void* d_out, int out_size) {
    const float* x     = (const float*)d_in[0];
    const float* gamma = (const float*)d_in[1];
    const float* beta  = (const float*)d_in[2];
    const float* wq    = (const float*)d_in[3];
    const float* bq    = (const float*)d_in[4];
    const float* wk    = (const float*)d_in[5];
    const float* bk    = (const float*)d_in[6];
    const float* wv    = (const float*)d_in[7];
    const float* bv    = (const float*)d_in[8];
    const float* wp    = (const float*)d_in[9];
    const float* bp    = (const float*)d_in[10];
    float* out = (float*)d_out;

    __half *xn16, *qkv16, *wt16, *vt16, *attn16, *ao16;
    float *attnF, *b3, *mean, *rstd;
    cudaGetSymbolAddress((void**)&xn16,   g_xn16);
    cudaGetSymbolAddress((void**)&qkv16,  g_qkv16);
    cudaGetSymbolAddress((void**)&wt16,   g_wt16);
    cudaGetSymbolAddress((void**)&vt16,   g_vt16);
    cudaGetSymbolAddress((void**)&attnF,  g_attn);
    cudaGetSymbolAddress((void**)&attn16, g_attn16);
    cudaGetSymbolAddress((void**)&ao16,   g_ao16);
    cudaGetSymbolAddress((void**)&b3,     g_b3);
    cudaGetSymbolAddress((void**)&mean,   g_mean);
    cudaGetSymbolAddress((void**)&rstd,   g_rstd);
    __half* q16 = qkv16;
    __half* k16 = qkv16 + (size_t)NBROWS*CD;
    __half* v16 = qkv16 + (size_t)2*NBROWS*CD;
    __half* wpT16 = wt16 + (size_t)3*CD*CD;

    // 1) GroupNorm stats + bias pack
    gn_stats_bias<<<65, 256>>>(x, mean, rstd, bq, bk, bv, b3);

    // 2) normalize -> fp16
    gn_norm<<<(NBROWS*CD/4)/256, 256>>>(x, gamma, beta, mean, rstd, xn16);

    // 3) weight transposes (fused, z=4) -> fp16
    wtrans4<<<dim3(CD/32, CD/32, 4), dim3(32, 8)>>>(wq, wk, wv, wp, wt16);

    // 4) fused qkv projections: z selects (wT, bias, out slab)
    gemm_h<true, false, true><<<dim3(CD/128, NBROWS/128, 3), 256>>>(
        xn16, wt16, b3, nullptr, qkv16, CD, CD, CD, CD, 1.f,
        0, (size_t)CD*CD, (size_t)NBROWS*CD, (size_t)CD);

    // 5) scores = q k^T * 1/sqrt(C) -> fp32
    const float scale = 0.044194173824159216f;
    gemm_h<false, false, false><<<dim3(HWN/128, HWN/128, BSZ), 256>>>(
        q16, k16, nullptr, nullptr, attnF, CD, CD, CD, HWN, scale,
        (size_t)HWN*CD, (size_t)HWN*CD, (size_t)HWN*HWN, 0);

    // 6) v transpose per batch (half)
    vtrans_h<<<dim3(CD/32, HWN/32, BSZ), dim3(32, 8)>>>(v16, vt16);

    // 7) softmax: fp32 in -> fp16 weights
    softmax_h<<<NBROWS, 256>>>(attnF, attn16);

    // 8) ao = attn @ v (K=4096, all-half inputs) -> fp16
    gemm_h<false, false, true><<<dim3(CD/128, HWN/128, BSZ), 256>>>(
        attn16, vt16, nullptr, nullptr, ao16, HWN, HWN, HWN, CD, 1.f,
        (size_t)HWN*HWN, (size_t)CD*HWN, (size_t)HWN*CD, 0);

    // 9) final projection + bias + residual -> fp32 d_out
    gemm_h<true, true, false><<<dim3(CD/128, NBROWS/128, 1), 256>>>(
        ao16, wpT16, bp, x, out, CD, CD, CD, CD, 1.f, 0, 0, 0, 0);
}

// round 15
// speedup vs baseline: 2.6682x; 1.0127x over previous
#include <cuda_runtime.h>
#include <cuda_fp16.h>
#include <math.h>
#include <stdint.h>

// Problem constants (fixed shapes)
#define BSZ 2
#define HWN 4096
#define CD  512
#define NBROWS (BSZ*HWN)      // 8192
#define NGROUPS 32

// ---------------------------------------------------------------------------
// Scratch (device globals; no allocations)
// ---------------------------------------------------------------------------
__device__ __half g_xn16 [(size_t)NBROWS*CD];
__device__ __half g_qkv16[(size_t)3*NBROWS*CD];        // q16 | k16 | v16
__device__ __half g_wt16 [(size_t)4*CD*CD];            // wqT|wkT|wvT|wpT (half)
__device__ __half g_vt16 [(size_t)BSZ*CD*HWN];         // v transposed per batch
__device__ float  g_attn [(size_t)BSZ*HWN*HWN];        // raw scores fp32 (134 MB)
__device__ __half g_attn16[(size_t)BSZ*HWN*HWN];       // softmax weights fp16 (67 MB)
__device__ __half g_ao16 [(size_t)NBROWS*CD];
__device__ float  g_b3   [3*CD];                       // bq|bk|bv packed
__device__ float  g_mean [BSZ*NGROUPS];
__device__ float  g_rstd [BSZ*NGROUPS];

// ---------------------------------------------------------------------------
// helpers
// ---------------------------------------------------------------------------
__device__ __forceinline__ uint32_t smem_u32(const void* p) {
    uint32_t a;
    asm("{ .reg .u64 t; cvta.to.shared.u64 t, %1; cvt.u32.u64 %0, t; }" : "=r"(a) : "l"(p));
    return a;
}
__device__ __forceinline__ void cp16(uint32_t dst, const void* src) {
    asm volatile("cp.async.cg.shared.global [%0], [%1], 16;" :: "r"(dst), "l"(src));
}
#define CP_COMMIT() asm volatile("cp.async.commit_group;")
#define CP_WAIT1()  asm volatile("cp.async.wait_group 1;")
#define CP_WAIT2()  asm volatile("cp.async.wait_group 2;")

__device__ __forceinline__ void ldmx4(uint32_t r[4], uint32_t addr) {
    asm volatile("ldmatrix.sync.aligned.m8n8.x4.shared.b16 {%0,%1,%2,%3}, [%4];"
        : "=r"(r[0]), "=r"(r[1]), "=r"(r[2]), "=r"(r[3]) : "r"(addr));
}
__device__ __forceinline__ void mma_f16(float c[4], const uint32_t a[4], const uint32_t b[2]) {
    asm volatile(
        "mma.sync.aligned.m16n8k16.row.col.f32.f16.f16.f32 "
        "{%0,%1,%2,%3}, {%4,%5,%6,%7}, {%8,%9}, {%0,%1,%2,%3};"
        : "+f"(c[0]), "+f"(c[1]), "+f"(c[2]), "+f"(c[3])
        : "r"(a[0]), "r"(a[1]), "r"(a[2]), "r"(a[3]), "r"(b[0]), "r"(b[1]));
}

// ---------------------------------------------------------------------------
// GroupNorm stats (+ fused bias pack in block 64)
// ---------------------------------------------------------------------------
__global__ void gn_stats_bias(const float* __restrict__ x,
                              float* __restrict__ mean, float* __restrict__ rstd,
                              const float* __restrict__ bq, const float* __restrict__ bk,
                              const float* __restrict__ bv, float* __restrict__ b3) {
    if (blockIdx.x == 64) {
        for (int i = threadIdx.x; i < CD; i += 256) {
            b3[i] = bq[i]; b3[CD + i] = bk[i]; b3[2*CD + i] = bv[i];
        }
        return;
    }
    __shared__ float shs[8], shss[8];
    const int bg = blockIdx.x;
    const int b = bg >> 5, g = bg & 31;
    const float4* xb = (const float4*)x + (size_t)b*524288 + g*4;
    float s = 0.f, ss = 0.f;
    for (int i = threadIdx.x; i < 16384; i += 256) {
        int n = i >> 2, j = i & 3;
        float4 vv = xb[(size_t)n*128 + j];
        s  += vv.x + vv.y + vv.z + vv.w;
        ss += vv.x*vv.x + vv.y*vv.y + vv.z*vv.z + vv.w*vv.w;
    }
    #pragma unroll
    for (int o = 16; o; o >>= 1) {
        s  += __shfl_xor_sync(0xffffffffu, s,  o);
        ss += __shfl_xor_sync(0xffffffffu, ss, o);
    }
    if ((threadIdx.x & 31) == 0) { shs[threadIdx.x>>5] = s; shss[threadIdx.x>>5] = ss; }
    __syncthreads();
    if (threadIdx.x == 0) {
        s = 0.f; ss = 0.f;
        #pragma unroll
        for (int w = 0; w < 8; w++) { s += shs[w]; ss += shss[w]; }
        float m   = s * (1.f/65536.f);
        float var = ss * (1.f/65536.f) - m*m;
        mean[bg] = m;
        rstd[bg] = rsqrtf(var + 1e-5f);
    }
}

// GroupNorm normalize -> fp16 output
__global__ void gn_norm(const float* __restrict__ x,
                        const float* __restrict__ gamma, const float* __restrict__ beta,
                        const float* __restrict__ mean, const float* __restrict__ rstd,
                        __half* __restrict__ xn) {
    const int idx = blockIdx.x * blockDim.x + threadIdx.x;   // float4 index
    float4 v = ((const float4*)x)[idx];
    const int c4 = idx & 127;
    const int b  = idx >> 19;
    const int g  = c4 >> 2;
    const int bg = b * 32 + g;
    const float m = mean[bg], r = rstd[bg];
    const float4 ga = ((const float4*)gamma)[c4];
    const float4 be = ((const float4*)beta)[c4];
    __half2 h0 = __float22half2_rn(make_float2((v.x - m)*r*ga.x + be.x, (v.y - m)*r*ga.y + be.y));
    __half2 h1 = __float22half2_rn(make_float2((v.z - m)*r*ga.z + be.z, (v.w - m)*r*ga.w + be.w));
    uint2 o = make_uint2(*(uint32_t*)&h0, *(uint32_t*)&h1);
    ((uint2*)xn)[idx] = o;
}

// 4 weight transposes fused (z selects weight), fp32 in -> fp16 out
__global__ void wtrans4(const float* __restrict__ w0, const float* __restrict__ w1,
                        const float* __restrict__ w2, const float* __restrict__ w3,
                        __half* __restrict__ out) {
    __shared__ float t[32][33];
    const float* src = blockIdx.z == 0 ? w0 : blockIdx.z == 1 ? w1 : blockIdx.z == 2 ? w2 : w3;
    __half* dst = out + (size_t)blockIdx.z * CD * CD;
    int c0 = blockIdx.x * 32, r0 = blockIdx.y * 32;
    int xx = threadIdx.x;
    #pragma unroll
    for (int y = threadIdx.y; y < 32; y += 8)
        t[y][xx] = src[(size_t)(r0 + y) * CD + c0 + xx];
    __syncthreads();
    #pragma unroll
    for (int y = threadIdx.y; y < 32; y += 8)
        dst[(size_t)(c0 + y) * CD + r0 + xx] = __float2half_rn(t[xx][y]);
}

// v16 [b][n][c] -> vt16 [b][c][n]
__global__ void vtrans_h(const __half* __restrict__ in, __half* __restrict__ out) {
    __shared__ __half t[32][33];
    const __half* inz = in + (size_t)blockIdx.z * HWN * CD;
    __half* outz = out + (size_t)blockIdx.z * CD * HWN;
    int c0 = blockIdx.x * 32, r0 = blockIdx.y * 32;
    int xx = threadIdx.x;
    #pragma unroll
    for (int y = threadIdx.y; y < 32; y += 8)
        t[y][xx] = inz[(size_t)(r0 + y) * CD + c0 + xx];
    __syncthreads();
    #pragma unroll
    for (int y = threadIdx.y; y < 32; y += 8)
        outz[(size_t)(c0 + y) * HWN + r0 + xx] = t[xx][y];
}

// ---------------------------------------------------------------------------
// fp16 NT GEMM, cp.async 4-stage ring + cross-tile ldmatrix double-buffering:
//   C[m][n] = alpha * sum_k A[m][k]*Bt[n][k]  (+bias[n]) (+res[m][n])
// CTA 128x128, BK=32 (2 k16 steps), 256 thr = 8 warps (2m x 4n), warp 64x32.
// SMEM rows 64B (32 half); 16B chunk c stored at c ^ ((row>>1)&3) ->
// conflict-free ldmatrix.  wait_group(1) on a 4-stage ring guarantees tile
// t+1 resident at iteration t, so next-tile fragments are prefetched into
// registers while the current tile's MMAs run: zero exposed ldmatrix latency.
// Dynamic SMEM: 4 stages x 8KB x 2 operands = 64 KB.
// ---------------------------------------------------------------------------
#define STAGE_BYTES 8192
#define GEMM_SMEM (4 * STAGE_BYTES * 2)

template<bool BIAS, bool RES, bool HOUT>
__global__ __launch_bounds__(256, 2)
void gemm_h(const __half* __restrict__ A, const __half* __restrict__ Bt,
            const float* __restrict__ bias, const float* __restrict__ res,
            void* __restrict__ Cptr,
            int K, int lda, int ldb, int ldc, float alpha,
            size_t zA, size_t zB, size_t zC, size_t zBias) {
    extern __shared__ uint32_t dynsm[];

    A  += blockIdx.z * zA;
    Bt += blockIdx.z * zB;
    const float* biasz = BIAS ? (bias + blockIdx.z * zBias) : bias;
    float*  Cf = (float*)Cptr  + (HOUT ? 0 : blockIdx.z * zC);
    __half* Ch = (__half*)Cptr + (HOUT ? blockIdx.z * zC : 0);

    const int tid = threadIdx.x;
    const int wid = tid >> 5;
    const int lane = tid & 31;
    const int gid = lane >> 2;
    const int tg  = lane & 3;
    const int wm = (wid & 1) * 64;
    const int wn = (wid >> 1) * 32;
    const int rowBlock = blockIdx.y * 128;
    const int colBlock = blockIdx.x * 128;

    // ---- cp.async staging coords
    const int srow = tid >> 2;          // 0..63
    const int sc   = tid & 3;           // 16B chunk in row
    const uint32_t sdst = (uint32_t)srow * 64 + (uint32_t)((sc ^ ((srow >> 1) & 3)) * 16);
    const __half* Asrc = A  + (size_t)(rowBlock + srow) * lda + sc * 8;
    const __half* Bsrc = Bt + (size_t)(colBlock + srow) * ldb + sc * 8;
    const uint32_t aS = smem_u32(dynsm);
    const uint32_t bS = aS + 4 * STAGE_BYTES;
    const size_t aRow64 = (size_t)64 * lda;
    const size_t bRow64 = (size_t)64 * ldb;

    // ---- ldmatrix per-lane fragment addresses
    const int rowA = wm + ((lane >> 3) & 1) * 8 + (lane & 7);
    const uint32_t offA = (uint32_t)rowA * 64 +
                          (uint32_t)(((( lane >> 4) & 1) ^ ((rowA >> 1) & 3)) * 16);
    const int rowB = wn + ((lane >> 4) & 1) * 8 + (lane & 7);
    const uint32_t offB = (uint32_t)rowB * 64 +
                          (uint32_t)(((( lane >> 3) & 1) ^ ((rowB >> 1) & 3)) * 16);

    float acc[4][4][4];
    #pragma unroll
    for (int mi = 0; mi < 4; mi++)
        #pragma unroll
        for (int ni = 0; ni < 4; ni++)
            #pragma unroll
            for (int r = 0; r < 4; r++) acc[mi][ni][r] = 0.f;

    const int T = K >> 5;     // BK=32 tiles (T >= 16 for all our shapes)

    // prologue: stage tiles 0,1,2
    #pragma unroll
    for (int st = 0; st < 3; st++) {
        cp16(aS + st * STAGE_BYTES + sdst,        Asrc + st * 32);
        cp16(aS + st * STAGE_BYTES + sdst + 4096, Asrc + aRow64 + st * 32);
        cp16(bS + st * STAGE_BYTES + sdst,        Bsrc + st * 32);
        cp16(bS + st * STAGE_BYTES + sdst + 4096, Bsrc + bRow64 + st * 32);
        CP_COMMIT();
    }
    CP_WAIT2();            // tile 0 resident
    __syncthreads();

    // fragment ping-pong buffers; preload tile 0 ks0 into buffer 0
    uint32_t af[2][4][4], bf[2][2][4];
    #pragma unroll
    for (int mi = 0; mi < 4; mi++) ldmx4(af[0][mi], aS + mi * 1024 + offA);
    #pragma unroll
    for (int p = 0; p < 2; p++)    ldmx4(bf[0][p], bS + p * 1024 + offB);

    int s = 0;
    for (int t = 0; t < T; t++) {
        CP_WAIT1();        // tiles <= t+1 resident
        __syncthreads();   // WAR guard for stage (t+3)%4 overwrite

        if (t + 3 < T) {
            int s3 = s + 3; if (s3 >= 4) s3 -= 4;
            const int kh = (t + 3) * 32;
            cp16(aS + s3 * STAGE_BYTES + sdst,        Asrc + kh);
            cp16(aS + s3 * STAGE_BYTES + sdst + 4096, Asrc + aRow64 + kh);
            cp16(bS + s3 * STAGE_BYTES + sdst,        Bsrc + kh);
            cp16(bS + s3 * STAGE_BYTES + sdst + 4096, Bsrc + bRow64 + kh);
        }
        CP_COMMIT();       // one group per iteration, always

        const uint32_t aBase = aS + s * STAGE_BYTES;
        const uint32_t bBase = bS + s * STAGE_BYTES;
        int s1 = s + 1; if (s1 >= 4) s1 -= 4;
        const uint32_t aNext = aS + s1 * STAGE_BYTES;
        const uint32_t bNext = bS + s1 * STAGE_BYTES;

        // load ks1 fragments (covered by ks0 MMAs below)
        #pragma unroll
        for (int mi = 0; mi < 4; mi++) ldmx4(af[1][mi], aBase + mi * 1024 + (offA ^ 32));
        #pragma unroll
        for (int p = 0; p < 2; p++)    ldmx4(bf[1][p], bBase + p * 1024 + (offB ^ 32));

        // MMAs on ks0 (buffer 0)
        #pragma unroll
        for (int mi = 0; mi < 4; mi++)
            #pragma unroll
            for (int ni = 0; ni < 4; ni++)
                mma_f16(acc[mi][ni], af[0][mi], &bf[0][ni >> 1][(ni & 1) * 2]);

        // prefetch next tile's ks0 fragments into buffer 0 (tile t+1 resident)
        if (t + 1 < T) {
            #pragma unroll
            for (int mi = 0; mi < 4; mi++) ldmx4(af[0][mi], aNext + mi * 1024 + offA);
            #pragma unroll
            for (int p = 0; p < 2; p++)    ldmx4(bf[0][p], bNext + p * 1024 + offB);
        }

        // MMAs on ks1 (buffer 1)
        #pragma unroll
        for (int mi = 0; mi < 4; mi++)
            #pragma unroll
            for (int ni = 0; ni < 4; ni++)
                mma_f16(acc[mi][ni], af[1][mi], &bf[1][ni >> 1][(ni & 1) * 2]);

        s = s1;
    }

    // epilogue (fragment layout identical to validated scalar version)
    #pragma unroll
    for (int mi = 0; mi < 4; mi++) {
        #pragma unroll
        for (int half = 0; half < 2; half++) {
            const size_t r = (size_t)(rowBlock + wm + mi * 16 + gid + half * 8);
            #pragma unroll
            for (int ni = 0; ni < 4; ni++) {
                const size_t c = (size_t)(colBlock + wn + ni * 8 + 2 * tg);
                float ox = acc[mi][ni][half * 2 + 0] * alpha;
                float oy = acc[mi][ni][half * 2 + 1] * alpha;
                if (BIAS) {
                    const float2 bb = *(const float2*)(biasz + c);
                    ox += bb.x; oy += bb.y;
                }
                if (RES) {
                    const float2 rr = *(const float2*)(res + r * ldc + c);
                    ox += rr.x; oy += rr.y;
                }
                if (HOUT) {
                    __half2 h = __float22half2_rn(make_float2(ox, oy));
                    *(__half2*)(Ch + r * ldc + c) = h;
                } else {
                    *(float2*)(Cf + r * ldc + c) = make_float2(ox, oy);
                }
            }
        }
    }
}

// ---------------------------------------------------------------------------
// Row softmax: fp32 scores in, fp16 weights out
// ---------------------------------------------------------------------------
__global__ void softmax_h(const float* __restrict__ S, __half* __restrict__ O) {
    __shared__ float sh[8];
    const size_t row = blockIdx.x;
    const float* p = S + row * 4096;
    __half* po = O + row * 4096;
    const int tid = threadIdx.x;
    float4 v[4];
    float mx = -1e30f;
    #pragma unroll
    for (int i = 0; i < 4; i++) {
        v[i] = ((const float4*)p)[tid + i*256];
        mx = fmaxf(mx, fmaxf(fmaxf(v[i].x, v[i].y), fmaxf(v[i].z, v[i].w)));
    }
    #pragma unroll
    for (int o = 16; o; o >>= 1) mx = fmaxf(mx, __shfl_xor_sync(0xffffffffu, mx, o));
    if ((tid & 31) == 0) sh[tid >> 5] = mx;
    __syncthreads();
    mx = sh[0];
    #pragma unroll
    for (int w = 1; w < 8; w++) mx = fmaxf(mx, sh[w]);

    float sum = 0.f;
    #pragma unroll
    for (int i = 0; i < 4; i++) {
        v[i].x = expf(v[i].x - mx); v[i].y = expf(v[i].y - mx);
        v[i].z = expf(v[i].z - mx); v[i].w = expf(v[i].w - mx);
        sum += v[i].x + v[i].y + v[i].z + v[i].w;
    }
    #pragma unroll
    for (int o = 16; o; o >>= 1) sum += __shfl_xor_sync(0xffffffffu, sum, o);
    __syncthreads();
    if ((tid & 31) == 0) sh[tid >> 5] = sum;
    __syncthreads();
    sum = 0.f;
    #pragma unroll
    for (int w = 0; w < 8; w++) sum += sh[w];
    const float inv = 1.f / sum;
    #pragma unroll
    for (int i = 0; i < 4; i++) {
        __half2 h0 = __float22half2_rn(make_float2(v[i].x * inv, v[i].y * inv));
        __half2 h1 = __float22half2_rn(make_float2(v[i].z * inv, v[i].w * inv));
        ((uint2*)po)[tid + i*256] = make_uint2(*(uint32_t*)&h0, *(uint32_t*)&h1);
    }
}

// ---------------------------------------------------------------------------
// launch
// ---------------------------------------------------------------------------
extern "C" void kernel_launch(void* const* d_in, const int* in_sizes, int n_in,
                              void* d_out, int out_size) {
    const float* x     = (const float*)d_in[0];
    const float* gamma = (const float*)d_in[1];
    const float* beta  = (const float*)d_in[2];
    const float* wq    = (const float*)d_in[3];
    const float* bq    = (const float*)d_in[4];
    const float* wk    = (const float*)d_in[5];
    const float* bk    = (const float*)d_in[6];
    const float* wv    = (const float*)d_in[7];
    const float* bv    = (const float*)d_in[8];
    const float* wp    = (const float*)d_in[9];
    const float* bp    = (const float*)d_in[10];
    float* out = (float*)d_out;

    __half *xn16, *qkv16, *wt16, *vt16, *attn16, *ao16;
    float *attnF, *b3, *mean, *rstd;
    cudaGetSymbolAddress((void**)&xn16,   g_xn16);
    cudaGetSymbolAddress((void**)&qkv16,  g_qkv16);
    cudaGetSymbolAddress((void**)&wt16,   g_wt16);
    cudaGetSymbolAddress((void**)&vt16,   g_vt16);
    cudaGetSymbolAddress((void**)&attnF,  g_attn);
    cudaGetSymbolAddress((void**)&attn16, g_attn16);
    cudaGetSymbolAddress((void**)&ao16,   g_ao16);
    cudaGetSymbolAddress((void**)&b3,     g_b3);
    cudaGetSymbolAddress((void**)&mean,   g_mean);
    cudaGetSymbolAddress((void**)&rstd,   g_rstd);
    __half* q16 = qkv16;
    __half* k16 = qkv16 + (size_t)NBROWS*CD;
    __half* v16 = qkv16 + (size_t)2*NBROWS*CD;
    __half* wpT16 = wt16 + (size_t)3*CD*CD;

    // allow 64 KB dynamic SMEM for the GEMM instantiations (host-side, capture-safe)
    cudaFuncSetAttribute(gemm_h<true,  false, true >, cudaFuncAttributeMaxDynamicSharedMemorySize, GEMM_SMEM);
    cudaFuncSetAttribute(gemm_h<false, false, false>, cudaFuncAttributeMaxDynamicSharedMemorySize, GEMM_SMEM);
    cudaFuncSetAttribute(gemm_h<false, false, true >, cudaFuncAttributeMaxDynamicSharedMemorySize, GEMM_SMEM);
    cudaFuncSetAttribute(gemm_h<true,  true,  false>, cudaFuncAttributeMaxDynamicSharedMemorySize, GEMM_SMEM);

    // 1) GroupNorm stats + bias pack
    gn_stats_bias<<<65, 256>>>(x, mean, rstd, bq, bk, bv, b3);

    // 2) normalize -> fp16
    gn_norm<<<(NBROWS*CD/4)/256, 256>>>(x, gamma, beta, mean, rstd, xn16);

    // 3) weight transposes (fused, z=4) -> fp16
    wtrans4<<<dim3(CD/32, CD/32, 4), dim3(32, 8)>>>(wq, wk, wv, wp, wt16);

    // 4) fused qkv projections: z selects (wT, bias, out slab)
    gemm_h<true, false, true><<<dim3(CD/128, NBROWS/128, 3), 256, GEMM_SMEM>>>(
        xn16, wt16, b3, nullptr, qkv16, CD, CD, CD, CD, 1.f,
        0, (size_t)CD*CD, (size_t)NBROWS*CD, (size_t)CD);

    // 5) scores = q k^T * 1/sqrt(C) -> fp32
    const float scale = 0.044194173824159216f;
    gemm_h<false, false, false><<<dim3(HWN/128, HWN/128, BSZ), 256, GEMM_SMEM>>>(
        q16, k16, nullptr, nullptr, attnF, CD, CD, CD, HWN, scale,
        (size_t)HWN*CD, (size_t)HWN*CD, (size_t)HWN*HWN, 0);

    // 6) v transpose per batch (half)
    vtrans_h<<<dim3(CD/32, HWN/32, BSZ), dim3(32, 8)>>>(v16, vt16);

    // 7) softmax: fp32 in -> fp16 weights
    softmax_h<<<NBROWS, 256>>>(attnF, attn16);

    // 8) ao = attn @ v (K=4096, all-half inputs) -> fp16
    gemm_h<false, false, true><<<dim3(CD/128, HWN/128, BSZ), 256, GEMM_SMEM>>>(
        attn16, vt16, nullptr, nullptr, ao16, HWN, HWN, HWN, CD, 1.f,
        (size_t)HWN*HWN, (size_t)CD*HWN, (size_t)HWN*CD, 0);

    // 9) final projection + bias + residual -> fp32 d_out
    gemm_h<true, true, false><<<dim3(CD/128, NBROWS/128, 1), 256, GEMM_SMEM>>>(
        ao16, wpT16, bp, x, out, CD, CD, CD, CD, 1.f, 0, 0, 0, 0);
}